// round 15
// baseline (speedup 1.0000x reference)
#include <cuda_runtime.h>
#include <stdint.h>

// XNOR binarized linear — occupancy-traded variant of the R14 champion.
// y[n,o] = (256 - 2*popc(xbits[n] ^ wbits[o])) * scale[o]
//
// R13/R14 showed per-warp ILP is register-capped. This version removes the
// depth-1 register prefetch (-16 regs) and moves scales to smem (-8 regs),
// capping at 96 regs -> 5 blocks/SM = 20 warps (was 16). The load->ballot
// stall this creates is covered by the extra warps + the L2 software
// prefetch (demand ldcs hits L2 at ~250cyc instead of DRAM 577).
// Keeps: ldcs reads, stcs writes, L2 prefetch, warp-broadcast ballots,
// weights in registers, exact magic epilogue.

constexpr int NROWS = 262144;
constexpr int DIM   = 256;   // IN == OUT
constexpr int WPR   = 8;     // packed words per row

constexpr int CHUNK_ROWS = 128;                 // rows per block (4 warps x 32)
constexpr int NBLOCKS    = NROWS / CHUNK_ROWS;  // 2048, one chunk per block

constexpr int PF_DIST = 8;                      // L2 prefetch lead (rows)

__device__ uint32_t g_wbits[DIM * WPR];

__device__ __forceinline__ void prefetch_l2(const void* p) {
    asm volatile("prefetch.global.L2 [%0];" :: "l"(p));
}

// ---------------------------------------------------------------------------
// Pre-kernel: pack weight sign bits (one warp per output row).
// Word (h*4+c), bit L  <->  element h*128 + 4L + c. Matches x packing below.
// ---------------------------------------------------------------------------
__global__ void pack_w_kernel(const float* __restrict__ w) {
    int warp = (blockIdx.x * blockDim.x + threadIdx.x) >> 5;
    int lane = threadIdx.x & 31;
    if (warp >= DIM) return;
    const float4* row = reinterpret_cast<const float4*>(w) + (size_t)warp * (DIM / 4);
#pragma unroll
    for (int h = 0; h < 2; ++h) {
        float4 v = row[h * 32 + lane];
        uint32_t m0 = __ballot_sync(0xFFFFFFFFu, v.x < 0.0f);
        uint32_t m1 = __ballot_sync(0xFFFFFFFFu, v.y < 0.0f);
        uint32_t m2 = __ballot_sync(0xFFFFFFFFu, v.z < 0.0f);
        uint32_t m3 = __ballot_sync(0xFFFFFFFFu, v.w < 0.0f);
        if (lane == 0) {
            *reinterpret_cast<uint4*>(&g_wbits[warp * WPR + h * 4]) =
                make_uint4(m0, m1, m2, m3);
        }
    }
}

// ---------------------------------------------------------------------------
// Main kernel: 128 threads (4 warps), one 128-row chunk per block.
// ---------------------------------------------------------------------------
__global__ void __launch_bounds__(128, 5)
xnor_occ_kernel(const float* __restrict__ x,
                const float* __restrict__ scale,
                float* __restrict__ out) {
    __shared__ float sscale[DIM];

    const int tid  = threadIdx.x;
    const int warp = tid >> 5;
    const int lane = tid & 31;

    // scales into smem (one coalesced pass)
    sscale[tid] = scale[tid];
    sscale[tid + 128] = scale[tid + 128];

    // Hoist weights for this lane's 8 output columns (strided o=32j+L).
    uint4 wlo[8], whi[8];
#pragma unroll
    for (int j = 0; j < 8; ++j) {
        int o = j * 32 + lane;
        wlo[j] = *reinterpret_cast<const uint4*>(&g_wbits[o * WPR]);
        whi[j] = *reinterpret_cast<const uint4*>(&g_wbits[o * WPR + 4]);
    }
    __syncthreads();

    constexpr uint32_t MAGIC256 = 0x4B400000u + 256u;   // 2^23*1.5 + 256

    const int row0 = blockIdx.x * CHUNK_ROWS + warp * 32;
    const float4* rp = reinterpret_cast<const float4*>(x) +
                       (size_t)row0 * (DIM / 4);
    float* orow = out + (size_t)row0 * DIM + lane;

    // warm the L2 prefetch window
#pragma unroll
    for (int r = 0; r < PF_DIST; ++r) {
        prefetch_l2(&rp[r * 64 + lane]);
        prefetch_l2(&rp[r * 64 + 32 + lane]);
    }

#pragma unroll 2
    for (int r = 0; r < 32; ++r) {
        // L2 prefetch for row r+PF_DIST (clamped)
        const int rf = (r + PF_DIST < 32) ? r + PF_DIST : 31;
        prefetch_l2(&rp[rf * 64 + lane]);
        prefetch_l2(&rp[rf * 64 + 32 + lane]);

        // demand-load this row (streaming; expected L2 hit via prefetch)
        float4 c0 = __ldcs(&rp[(size_t)r * 64 + lane]);
        float4 c1 = __ldcs(&rp[(size_t)r * 64 + 32 + lane]);

        // transpose row signs into 8 words, broadcast to all lanes
        uint32_t b0 = __ballot_sync(0xFFFFFFFFu, c0.x < 0.0f);
        uint32_t b1 = __ballot_sync(0xFFFFFFFFu, c0.y < 0.0f);
        uint32_t b2 = __ballot_sync(0xFFFFFFFFu, c0.z < 0.0f);
        uint32_t b3 = __ballot_sync(0xFFFFFFFFu, c0.w < 0.0f);
        uint32_t b4 = __ballot_sync(0xFFFFFFFFu, c1.x < 0.0f);
        uint32_t b5 = __ballot_sync(0xFFFFFFFFu, c1.y < 0.0f);
        uint32_t b6 = __ballot_sync(0xFFFFFFFFu, c1.z < 0.0f);
        uint32_t b7 = __ballot_sync(0xFFFFFFFFu, c1.w < 0.0f);

        // 8 independent output-group chains (ILP)
#pragma unroll
        for (int j = 0; j < 8; ++j) {
            int p = __popc(b0 ^ wlo[j].x) + __popc(b1 ^ wlo[j].y) +
                    __popc(b2 ^ wlo[j].z) + __popc(b3 ^ wlo[j].w) +
                    __popc(b4 ^ whi[j].x) + __popc(b5 ^ whi[j].y) +
                    __popc(b6 ^ whi[j].z) + __popc(b7 ^ whi[j].w);
            // exact: t = magic + (256-2p); fd = float(256-2p) exactly
            uint32_t t = MAGIC256 - 2u * (uint32_t)p;       // IMAD
            float fd = __uint_as_float(t) - 12582912.0f;    // FADD (exact)
            __stcs(&orow[j * 32], fd * sscale[j * 32 + lane]);  // LDS + STG
        }

        orow += DIM;
    }
}

// ---------------------------------------------------------------------------
// kernel_launch: d_in[0]=x [N,256] f32, d_in[1]=weight [256,256] f32,
//                d_in[2]=scale [1,256] f32; d_out = y [N,256] f32.
// ---------------------------------------------------------------------------
extern "C" void kernel_launch(void* const* d_in, const int* in_sizes, int n_in,
                              void* d_out, int out_size) {
    const float* x      = (const float*)d_in[0];
    const float* weight = (const float*)d_in[1];
    const float* scale  = (const float*)d_in[2];
    float* out          = (float*)d_out;
    (void)in_sizes; (void)n_in; (void)out_size;

    pack_w_kernel<<<32, 256>>>(weight);
    xnor_occ_kernel<<<NBLOCKS, 128>>>(x, scale, out);
}

// round 16
// speedup vs baseline: 1.0220x; 1.0220x over previous
#include <cuda_runtime.h>
#include <stdint.h>

// XNOR binarized linear — R14 champion + half the weights in smem to afford
// 5 blocks/SM (20 warps) WITHOUT giving up the depth-1 register prefetch.
// y[n,o] = (256 - 2*popc(xbits[n] ^ wbits[o])) * scale[o]
//
// R13: deeper reg prefetch at 128-reg cap -> regressed (spills).
// R15: +warps, -reg prefetch -> regressed (lost ILP).
// R16: keep ILP, free 40 regs (whi + scales -> smem), cap 96 regs, 20 warps.
// Keeps: ldcs reads, stcs writes, L2 prefetch, ballots, exact magic epilogue.

constexpr int NROWS = 262144;
constexpr int DIM   = 256;   // IN == OUT
constexpr int WPR   = 8;     // packed words per row

constexpr int CHUNK_ROWS = 128;                 // rows per block (4 warps x 32)
constexpr int NBLOCKS    = NROWS / CHUNK_ROWS;  // 2048, one chunk per block

constexpr int PF_DIST = 6;                      // L2 prefetch lead (rows)

__device__ uint32_t g_wbits[DIM * WPR];

__device__ __forceinline__ void prefetch_l2(const void* p) {
    asm volatile("prefetch.global.L2 [%0];" :: "l"(p));
}

// ---------------------------------------------------------------------------
// Pre-kernel: pack weight sign bits (one warp per output row).
// Word (h*4+c), bit L  <->  element h*128 + 4L + c. Matches x packing below.
// ---------------------------------------------------------------------------
__global__ void pack_w_kernel(const float* __restrict__ w) {
    int warp = (blockIdx.x * blockDim.x + threadIdx.x) >> 5;
    int lane = threadIdx.x & 31;
    if (warp >= DIM) return;
    const float4* row = reinterpret_cast<const float4*>(w) + (size_t)warp * (DIM / 4);
#pragma unroll
    for (int h = 0; h < 2; ++h) {
        float4 v = row[h * 32 + lane];
        uint32_t m0 = __ballot_sync(0xFFFFFFFFu, v.x < 0.0f);
        uint32_t m1 = __ballot_sync(0xFFFFFFFFu, v.y < 0.0f);
        uint32_t m2 = __ballot_sync(0xFFFFFFFFu, v.z < 0.0f);
        uint32_t m3 = __ballot_sync(0xFFFFFFFFu, v.w < 0.0f);
        if (lane == 0) {
            *reinterpret_cast<uint4*>(&g_wbits[warp * WPR + h * 4]) =
                make_uint4(m0, m1, m2, m3);
        }
    }
}

// ---------------------------------------------------------------------------
// Main kernel: 128 threads (4 warps), one 128-row chunk per block.
// ---------------------------------------------------------------------------
__global__ void __launch_bounds__(128, 5)
xnor_hybrid_kernel(const float* __restrict__ x,
                   const float* __restrict__ scale,
                   float* __restrict__ out) {
    __shared__ uint4 swhi[DIM];      // high 4 weight words per output (4 KB)
    __shared__ float sscale[DIM];    // scales (1 KB)

    const int tid  = threadIdx.x;
    const int warp = tid >> 5;
    const int lane = tid & 31;

    // fill smem: whi + scales (coalesced, once per block)
    {
        const uint4* gw = reinterpret_cast<const uint4*>(g_wbits);
        swhi[tid]       = gw[tid * 2 + 1];          // odd uint4 = high half
        swhi[tid + 128] = gw[(tid + 128) * 2 + 1];
        sscale[tid]       = scale[tid];
        sscale[tid + 128] = scale[tid + 128];
    }

    // low half of weights in registers for this lane's 8 outputs (o = 32j+L)
    uint4 wlo[8];
#pragma unroll
    for (int j = 0; j < 8; ++j) {
        wlo[j] = *reinterpret_cast<const uint4*>(&g_wbits[(j * 32 + lane) * WPR]);
    }
    __syncthreads();

    constexpr uint32_t MAGIC256 = 0x4B400000u + 256u;   // 2^23*1.5 + 256

    const int row0 = blockIdx.x * CHUNK_ROWS + warp * 32;
    const float4* rp = reinterpret_cast<const float4*>(x) +
                       (size_t)row0 * (DIM / 4);
    float* orow = out + (size_t)row0 * DIM + lane;

    // warm the L2 prefetch window
#pragma unroll
    for (int r = 1; r < PF_DIST; ++r) {
        prefetch_l2(&rp[r * 64 + lane]);
        prefetch_l2(&rp[r * 64 + 32 + lane]);
    }

    // depth-1 register prefetch of the first row (streaming loads)
    float4 c0 = __ldcs(&rp[lane]);
    float4 c1 = __ldcs(&rp[32 + lane]);

#pragma unroll 2
    for (int r = 0; r < 32; ++r) {
        // L2 prefetch for row r+PF_DIST (clamped)
        const int rf = (r + PF_DIST < 32) ? r + PF_DIST : 31;
        prefetch_l2(&rp[rf * 64 + lane]);
        prefetch_l2(&rp[rf * 64 + 32 + lane]);

        // register prefetch next row (clamped on last iteration)
        const float4* np = rp + (size_t)(r + 1 < 32 ? r + 1 : r) * (DIM / 4);
        float4 n0 = __ldcs(&np[lane]);
        float4 n1 = __ldcs(&np[32 + lane]);

        // transpose row signs into 8 words, broadcast to all lanes
        uint32_t b0 = __ballot_sync(0xFFFFFFFFu, c0.x < 0.0f);
        uint32_t b1 = __ballot_sync(0xFFFFFFFFu, c0.y < 0.0f);
        uint32_t b2 = __ballot_sync(0xFFFFFFFFu, c0.z < 0.0f);
        uint32_t b3 = __ballot_sync(0xFFFFFFFFu, c0.w < 0.0f);
        uint32_t b4 = __ballot_sync(0xFFFFFFFFu, c1.x < 0.0f);
        uint32_t b5 = __ballot_sync(0xFFFFFFFFu, c1.y < 0.0f);
        uint32_t b6 = __ballot_sync(0xFFFFFFFFu, c1.z < 0.0f);
        uint32_t b7 = __ballot_sync(0xFFFFFFFFu, c1.w < 0.0f);

        // 8 independent output-group chains (ILP); whi streamed from smem
#pragma unroll
        for (int j = 0; j < 8; ++j) {
            const uint4 whij = swhi[j * 32 + lane];     // LDS.128
            int p = __popc(b0 ^ wlo[j].x) + __popc(b1 ^ wlo[j].y) +
                    __popc(b2 ^ wlo[j].z) + __popc(b3 ^ wlo[j].w) +
                    __popc(b4 ^ whij.x)   + __popc(b5 ^ whij.y) +
                    __popc(b6 ^ whij.z)   + __popc(b7 ^ whij.w);
            // exact: t = magic + (256-2p); fd = float(256-2p) exactly
            uint32_t t = MAGIC256 - 2u * (uint32_t)p;       // IMAD
            float fd = __uint_as_float(t) - 12582912.0f;    // FADD (exact)
            __stcs(&orow[j * 32], fd * sscale[j * 32 + lane]);  // streaming STG
        }

        c0 = n0; c1 = n1;
        orow += DIM;
    }
}

// ---------------------------------------------------------------------------
// kernel_launch: d_in[0]=x [N,256] f32, d_in[1]=weight [256,256] f32,
//                d_in[2]=scale [1,256] f32; d_out = y [N,256] f32.
// ---------------------------------------------------------------------------
extern "C" void kernel_launch(void* const* d_in, const int* in_sizes, int n_in,
                              void* d_out, int out_size) {
    const float* x      = (const float*)d_in[0];
    const float* weight = (const float*)d_in[1];
    const float* scale  = (const float*)d_in[2];
    float* out          = (float*)d_out;
    (void)in_sizes; (void)n_in; (void)out_size;

    pack_w_kernel<<<32, 256>>>(weight);
    xnor_hybrid_kernel<<<NBLOCKS, 128>>>(x, scale, out);
}

// round 17
// speedup vs baseline: 1.0695x; 1.0465x over previous
#include <cuda_runtime.h>
#include <cuda_pipeline.h>
#include <stdint.h>

// XNOR binarized linear — cp.async (LDGSTS) pipelined read path.
// y[n,o] = (256 - 2*popc(xbits[n] ^ wbits[o])) * scale[o]
//
// 16 rounds pinned at ~47% DRAM: register-file cannot hold enough in-flight
// loads alongside 64 weight regs. cp.async tracks completion via groups (no
// registers, no scoreboard), letting each warp keep 8 rows (8KB) in flight
// in a smem ring. 20 warps/SM x 8KB = 160KB/SM in-flight reads.
// Each lane copies exactly the 16B it later consumes -> per-thread
// wait_prior is sufficient, no extra sync.
// Keeps: weights in regs, warp-broadcast ballots, exact magic epilogue,
// __stcs streaming stores.

constexpr int NROWS = 262144;
constexpr int DIM   = 256;   // IN == OUT
constexpr int WPR   = 8;     // packed words per row

constexpr int CHUNK_ROWS = 128;                 // rows per block (4 warps x 32)
constexpr int NBLOCKS    = NROWS / CHUNK_ROWS;  // 2048, one chunk per block

constexpr int NSTAGE = 8;                       // smem ring depth (rows/warp)

__device__ uint32_t g_wbits[DIM * WPR];

// ---------------------------------------------------------------------------
// Pre-kernel: pack weight sign bits (one warp per output row).
// Word (h*4+c), bit L  <->  element h*128 + 4L + c. Matches x packing below.
// ---------------------------------------------------------------------------
__global__ void pack_w_kernel(const float* __restrict__ w) {
    int warp = (blockIdx.x * blockDim.x + threadIdx.x) >> 5;
    int lane = threadIdx.x & 31;
    if (warp >= DIM) return;
    const float4* row = reinterpret_cast<const float4*>(w) + (size_t)warp * (DIM / 4);
#pragma unroll
    for (int h = 0; h < 2; ++h) {
        float4 v = row[h * 32 + lane];
        uint32_t m0 = __ballot_sync(0xFFFFFFFFu, v.x < 0.0f);
        uint32_t m1 = __ballot_sync(0xFFFFFFFFu, v.y < 0.0f);
        uint32_t m2 = __ballot_sync(0xFFFFFFFFu, v.z < 0.0f);
        uint32_t m3 = __ballot_sync(0xFFFFFFFFu, v.w < 0.0f);
        if (lane == 0) {
            *reinterpret_cast<uint4*>(&g_wbits[warp * WPR + h * 4]) =
                make_uint4(m0, m1, m2, m3);
        }
    }
}

// ---------------------------------------------------------------------------
// Main kernel: 128 threads (4 warps), one 128-row chunk per block.
// ---------------------------------------------------------------------------
__global__ void __launch_bounds__(128, 5)
xnor_cpasync_kernel(const float* __restrict__ x,
                    const float* __restrict__ scale,
                    float* __restrict__ out) {
    __shared__ float4 sbuf[4][NSTAGE][64];   // 4 warps x 8 rows x 1KB = 32 KB
    __shared__ float  sscale[DIM];           // 1 KB

    const int tid  = threadIdx.x;
    const int warp = tid >> 5;
    const int lane = tid & 31;

    // scales into smem
    sscale[tid]       = scale[tid];
    sscale[tid + 128] = scale[tid + 128];

    // weights in registers for this lane's 8 outputs (o = 32j + lane)
    uint4 wlo[8], whi[8];
#pragma unroll
    for (int j = 0; j < 8; ++j) {
        int o = j * 32 + lane;
        wlo[j] = *reinterpret_cast<const uint4*>(&g_wbits[o * WPR]);
        whi[j] = *reinterpret_cast<const uint4*>(&g_wbits[o * WPR + 4]);
    }
    __syncthreads();

    constexpr uint32_t MAGIC256 = 0x4B400000u + 256u;   // 2^23*1.5 + 256

    const int row0 = blockIdx.x * CHUNK_ROWS + warp * 32;
    const float4* rp = reinterpret_cast<const float4*>(x) +
                       (size_t)row0 * (DIM / 4);
    float* orow = out + (size_t)row0 * DIM + lane;

    // ---- prologue: issue rows 0..NSTAGE-2 into the ring ----
#pragma unroll
    for (int r = 0; r < NSTAGE - 1; ++r) {
        __pipeline_memcpy_async(&sbuf[warp][r][lane],
                                &rp[(size_t)r * 64 + lane], 16);
        __pipeline_memcpy_async(&sbuf[warp][r][32 + lane],
                                &rp[(size_t)r * 64 + 32 + lane], 16);
        __pipeline_commit();
    }

    // ---- steady state ----
#pragma unroll 2
    for (int r = 0; r < 32; ++r) {
        // issue row r+NSTAGE-1 (if any), always commit to keep group count
        const int rn = r + NSTAGE - 1;
        if (rn < 32) {
            const int st = rn & (NSTAGE - 1);
            __pipeline_memcpy_async(&sbuf[warp][st][lane],
                                    &rp[(size_t)rn * 64 + lane], 16);
            __pipeline_memcpy_async(&sbuf[warp][st][32 + lane],
                                    &rp[(size_t)rn * 64 + 32 + lane], 16);
        }
        __pipeline_commit();
        __pipeline_wait_prior(NSTAGE - 1);   // row r's group complete

        // consume row r (each lane reads the 16B it copied itself)
        const int sc = r & (NSTAGE - 1);
        float4 c0 = sbuf[warp][sc][lane];
        float4 c1 = sbuf[warp][sc][32 + lane];

        // transpose row signs into 8 words, broadcast to all lanes
        uint32_t b0 = __ballot_sync(0xFFFFFFFFu, c0.x < 0.0f);
        uint32_t b1 = __ballot_sync(0xFFFFFFFFu, c0.y < 0.0f);
        uint32_t b2 = __ballot_sync(0xFFFFFFFFu, c0.z < 0.0f);
        uint32_t b3 = __ballot_sync(0xFFFFFFFFu, c0.w < 0.0f);
        uint32_t b4 = __ballot_sync(0xFFFFFFFFu, c1.x < 0.0f);
        uint32_t b5 = __ballot_sync(0xFFFFFFFFu, c1.y < 0.0f);
        uint32_t b6 = __ballot_sync(0xFFFFFFFFu, c1.z < 0.0f);
        uint32_t b7 = __ballot_sync(0xFFFFFFFFu, c1.w < 0.0f);

        // 8 independent output-group chains (ILP)
#pragma unroll
        for (int j = 0; j < 8; ++j) {
            int p = __popc(b0 ^ wlo[j].x) + __popc(b1 ^ wlo[j].y) +
                    __popc(b2 ^ wlo[j].z) + __popc(b3 ^ wlo[j].w) +
                    __popc(b4 ^ whi[j].x) + __popc(b5 ^ whi[j].y) +
                    __popc(b6 ^ whi[j].z) + __popc(b7 ^ whi[j].w);
            // exact: t = magic + (256-2p); fd = float(256-2p) exactly
            uint32_t t = MAGIC256 - 2u * (uint32_t)p;       // IMAD
            float fd = __uint_as_float(t) - 12582912.0f;    // FADD (exact)
            __stcs(&orow[j * 32], fd * sscale[j * 32 + lane]);  // streaming STG
        }

        orow += DIM;
    }
}

// ---------------------------------------------------------------------------
// kernel_launch: d_in[0]=x [N,256] f32, d_in[1]=weight [256,256] f32,
//                d_in[2]=scale [1,256] f32; d_out = y [N,256] f32.
// ---------------------------------------------------------------------------
extern "C" void kernel_launch(void* const* d_in, const int* in_sizes, int n_in,
                              void* d_out, int out_size) {
    const float* x      = (const float*)d_in[0];
    const float* weight = (const float*)d_in[1];
    const float* scale  = (const float*)d_in[2];
    float* out          = (float*)d_out;
    (void)in_sizes; (void)n_in; (void)out_size;

    pack_w_kernel<<<32, 256>>>(weight);
    xnor_cpasync_kernel<<<NBLOCKS, 128>>>(x, scale, out);
}